// round 4
// baseline (speedup 1.0000x reference)
#include <cuda_runtime.h>
#include <math.h>

#define NB 8
#define DIMC 256
#define HH 64
#define WW 64
#define HW 4096
#define NHEADS 8
#define DHEAD 32
#define INNER 256
#define BHN 64
#define FFIC 1024
#define TOPH 16
#define TOPW 16
#define NSEL 256

// ---------------- scratch (static device memory; no allocation allowed) ------
__device__ float g_xn[(size_t)NB*DIMC*HW];
__device__ float g_qkv[(size_t)NB*3*INNER*HW];
__device__ float g_qrow[BHN*DHEAD*HH];
__device__ float g_kheight[BHN*DHEAD*HH];
__device__ float g_qprobe[BHN*DHEAD];
__device__ int   g_toph[BHN*TOPH];
__device__ int   g_topw[BHN*TOPW];
__device__ float g_kf[BHN*NSEL*DHEAD];
__device__ float g_vf[BHN*NSEL*DHEAD];
__device__ float g_attninner[(size_t)NB*INNER*HW];
__device__ float g_combined[(size_t)NB*2*DIMC*HW];
__device__ float g_attnout[(size_t)NB*DIMC*HW];
__device__ float g_h1[(size_t)NB*FFIC*HW];
__device__ float g_h[(size_t)NB*FFIC*HW];
__device__ float g_c2[(size_t)NB*FFIC*HW];
__device__ float g_ff2[(size_t)NB*DIMC*HW];

// ---------------- channel layernorm (over C at each b,h,w) -------------------
__global__ void ln_kernel(const float* __restrict__ x, const float* __restrict__ g,
                          const float* __restrict__ bb, float* __restrict__ out) {
    int pos = blockIdx.x * 256 + threadIdx.x;     // 0..4095
    int b = blockIdx.y;
    const float* xb = x + (size_t)b * DIMC * HW + pos;
    float s = 0.f, ss = 0.f;
    #pragma unroll 8
    for (int c = 0; c < DIMC; c++) {
        float v = xb[(size_t)c * HW];
        s += v; ss += v * v;
    }
    float mean = s * (1.f / DIMC);
    float var  = ss * (1.f / DIMC) - mean * mean;
    float rstd = rsqrtf(var + 1e-5f);
    float* ob = out + (size_t)b * DIMC * HW + pos;
    #pragma unroll 8
    for (int c = 0; c < DIMC; c++) {
        float v = xb[(size_t)c * HW];
        ob[(size_t)c * HW] = (v - mean) * rstd * g[c] + bb[c];
    }
}

// ---------------- SGEMM: C[bz] = A(MxK) @ B[bz](KxN) (+bias)(+resid) ---------
// all row-major. M%128==0, N%128==0, K%16==0 required.
// Ping-pong smem double buffering + register prefetch: one barrier per K-tile.
__global__ __launch_bounds__(256)
void sgemm(const float* __restrict__ A, const float* __restrict__ B,
           float* __restrict__ C, const float* __restrict__ bias,
           const float* __restrict__ resid,
           int M, int N, int K,
           size_t bStride, size_t cStride, size_t rStride)
{
    const int bz = blockIdx.z;
    const float* Bb = B + bz * bStride;
    float* Cb = C + bz * cStride;
    const float* Rb = resid ? resid + bz * rStride : nullptr;

    __shared__ float As[2][16][128];
    __shared__ float Bs[2][16][128];

    const int tid  = threadIdx.x;
    const int trow = tid / 16;     // 0..15
    const int tcol = tid % 16;     // 0..15
    const int rowBase = blockIdx.y * 128;
    const int colBase = blockIdx.x * 128;

    float acc[8][8];
    #pragma unroll
    for (int i = 0; i < 8; i++)
        #pragma unroll
        for (int j = 0; j < 8; j++) acc[i][j] = 0.f;

    const int aRow0 = tid >> 2;          // 0..63 (+64)
    const int aK4   = (tid & 3) << 2;    // k offset 0,4,8,12
    const int bRow0 = tid >> 5;          // 0..7 (+8)
    const int bCol  = (tid & 31) << 2;   // 0..124

    float4 pa[2], pb[2];
    // prefetch tile 0 into registers, store to buffer 0
    #pragma unroll
    for (int i = 0; i < 2; i++)
        pa[i] = *reinterpret_cast<const float4*>(&A[(size_t)(rowBase + aRow0 + i * 64) * K + aK4]);
    #pragma unroll
    for (int i = 0; i < 2; i++)
        pb[i] = *reinterpret_cast<const float4*>(&Bb[(size_t)(bRow0 + i * 8) * N + colBase + bCol]);
    #pragma unroll
    for (int i = 0; i < 2; i++) {
        int r = aRow0 + i * 64;
        As[0][aK4 + 0][r] = pa[i].x;
        As[0][aK4 + 1][r] = pa[i].y;
        As[0][aK4 + 2][r] = pa[i].z;
        As[0][aK4 + 3][r] = pa[i].w;
        *reinterpret_cast<float4*>(&Bs[0][bRow0 + i * 8][bCol]) = pb[i];
    }
    __syncthreads();

    const int nTiles = K >> 4;
    for (int kt = 0; kt < nTiles; kt++) {
        const int buf = kt & 1;
        // issue LDGs for tile kt+1 (latency hidden under the FFMA block below)
        if (kt + 1 < nTiles) {
            int kn = (kt + 1) << 4;
            #pragma unroll
            for (int i = 0; i < 2; i++)
                pa[i] = *reinterpret_cast<const float4*>(&A[(size_t)(rowBase + aRow0 + i * 64) * K + kn + aK4]);
            #pragma unroll
            for (int i = 0; i < 2; i++)
                pb[i] = *reinterpret_cast<const float4*>(&Bb[(size_t)(kn + bRow0 + i * 8) * N + colBase + bCol]);
        }

        #pragma unroll
        for (int kk = 0; kk < 16; kk++) {
            float ra[8], rb[8];
            float4 a0 = *reinterpret_cast<const float4*>(&As[buf][kk][trow * 8]);
            float4 a1 = *reinterpret_cast<const float4*>(&As[buf][kk][trow * 8 + 4]);
            float4 b0 = *reinterpret_cast<const float4*>(&Bs[buf][kk][tcol * 8]);
            float4 b1 = *reinterpret_cast<const float4*>(&Bs[buf][kk][tcol * 8 + 4]);
            ra[0]=a0.x; ra[1]=a0.y; ra[2]=a0.z; ra[3]=a0.w;
            ra[4]=a1.x; ra[5]=a1.y; ra[6]=a1.z; ra[7]=a1.w;
            rb[0]=b0.x; rb[1]=b0.y; rb[2]=b0.z; rb[3]=b0.w;
            rb[4]=b1.x; rb[5]=b1.y; rb[6]=b1.z; rb[7]=b1.w;
            #pragma unroll
            for (int i = 0; i < 8; i++)
                #pragma unroll
                for (int j = 0; j < 8; j++)
                    acc[i][j] += ra[i] * rb[j];
        }

        // store tile kt+1 into the other buffer, then one barrier
        if (kt + 1 < nTiles) {
            const int nb = buf ^ 1;
            #pragma unroll
            for (int i = 0; i < 2; i++) {
                int r = aRow0 + i * 64;
                As[nb][aK4 + 0][r] = pa[i].x;
                As[nb][aK4 + 1][r] = pa[i].y;
                As[nb][aK4 + 2][r] = pa[i].z;
                As[nb][aK4 + 3][r] = pa[i].w;
                *reinterpret_cast<float4*>(&Bs[nb][bRow0 + i * 8][bCol]) = pb[i];
            }
            __syncthreads();
        }
    }
    #pragma unroll
    for (int i = 0; i < 8; i++) {
        int m = rowBase + trow * 8 + i;
        float bv = bias ? bias[m] : 0.f;
        #pragma unroll
        for (int j = 0; j < 8; j++) {
            int n = colBase + tcol * 8 + j;
            float v = acc[i][j] + bv;
            if (Rb) v += Rb[(size_t)m * N + n];
            Cb[(size_t)m * N + n] = v;
        }
    }
}

// ---------------- l2 norm along W for q/k rows + row sums --------------------
__global__ void l2norm_kernel(float* __restrict__ qkv, float* __restrict__ qrow,
                              float* __restrict__ kheight) {
    int gw   = (blockIdx.x * blockDim.x + threadIdx.x) >> 5;
    int lane = threadIdx.x & 31;
    const int RPP = BHN * DHEAD * HH;   // rows per part
    int part = (gw >= RPP) ? 1 : 0;
    int r = gw - part * RPP;
    int bh  = r / (DHEAD * HH);
    int rem = r % (DHEAD * HH);
    int c = rem / HH;
    int h = rem % HH;
    int b = bh >> 3, hd = bh & 7;
    int ch = part * INNER + hd * DHEAD + c;
    float* row = qkv + ((size_t)(b * 3 * INNER + ch) * HH + h) * WW;
    float x0 = row[lane], x1 = row[lane + 32];
    float ss = x0 * x0 + x1 * x1;
    #pragma unroll
    for (int o = 16; o > 0; o >>= 1) ss += __shfl_xor_sync(0xffffffffu, ss, o);
    float n  = sqrtf(ss);
    float sc = 1.f / fmaxf(n, 1e-12f);
    x0 *= sc; x1 *= sc;
    row[lane] = x0; row[lane + 32] = x1;
    float rs = x0 + x1;
    #pragma unroll
    for (int o = 16; o > 0; o >>= 1) rs += __shfl_xor_sync(0xffffffffu, rs, o);
    if (lane == 0) {
        float* dst = part ? kheight : qrow;
        dst[(bh * DHEAD + c) * HH + h] = rs;
    }
}

// ---------------- q_probe, score_r, top-16 rows ------------------------------
__global__ void scorer_kernel(const float* __restrict__ qrow, const float* __restrict__ kheight,
                              float* __restrict__ qprobe, int* __restrict__ toph) {
    __shared__ float qp[DHEAD];
    __shared__ float sc[HH];
    int bh = blockIdx.x;
    int tid = threadIdx.x;
    if (tid < DHEAD) {
        float s = 0.f;
        const float* qr = qrow + (bh * DHEAD + tid) * HH;
        for (int h = 0; h < HH; h++) s += qr[h];
        qp[tid] = s;
        qprobe[bh * DHEAD + tid] = s;
    }
    __syncthreads();
    if (tid < HH) {
        float s = 0.f;
        const float* kh = kheight + bh * DHEAD * HH;
        for (int c = 0; c < DHEAD; c++) s += qp[c] * kh[c * HH + tid];
        sc[tid] = s;
    }
    __syncthreads();
    if (tid == 0) {
        for (int i = 0; i < TOPH; i++) {
            float best = -INFINITY; int bi = 0;
            for (int h = 0; h < HH; h++) if (sc[h] > best) { best = sc[h]; bi = h; }
            toph[bh * TOPH + i] = bi;
            sc[bi] = -INFINITY;
        }
    }
}

// ---------------- k_width, score_c, top-16 cols, gather kf/vf ----------------
__global__ void select_gather_kernel(const float* __restrict__ qkv, const float* __restrict__ qprobe,
                                     const int* __restrict__ toph, int* __restrict__ topw,
                                     float* __restrict__ kf, float* __restrict__ vf) {
    __shared__ float kw[DHEAD * WW];
    __shared__ float sc[WW];
    __shared__ int th[TOPH];
    __shared__ int tw[TOPW];
    int bh = blockIdx.x;
    int tid = threadIdx.x;
    int b = bh >> 3, hd = bh & 7;
    if (tid < TOPH) th[tid] = toph[bh * TOPH + tid];
    __syncthreads();
    const size_t kbase = (size_t)(b * 3 * INNER + INNER + hd * DHEAD) * HW;
    for (int idx = tid; idx < DHEAD * WW; idx += 256) {
        int c = idx >> 6, w = idx & 63;
        float s = 0.f;
        #pragma unroll
        for (int i = 0; i < TOPH; i++)
            s += qkv[kbase + (size_t)c * HW + th[i] * WW + w];
        kw[idx] = s;
    }
    __syncthreads();
    if (tid < WW) {
        const float* qp = qprobe + bh * DHEAD;
        float s = 0.f;
        for (int c = 0; c < DHEAD; c++) s += qp[c] * kw[c * WW + tid];
        sc[tid] = s;
    }
    __syncthreads();
    if (tid == 0) {
        for (int i = 0; i < TOPW; i++) {
            float best = -INFINITY; int bi = 0;
            for (int w = 0; w < WW; w++) if (sc[w] > best) { best = sc[w]; bi = w; }
            tw[i] = bi; topw[bh * TOPW + i] = bi;
            sc[bi] = -INFINITY;
        }
    }
    __syncthreads();
    {
        const size_t vbase = (size_t)(b * 3 * INNER + 2 * INNER + hd * DHEAD) * HW;
        int j = tid;                    // 256 threads = 256 selected keys
        int hi = th[j >> 4];
        int wi = tw[j & 15];
        size_t off = (size_t)hi * WW + wi;
        float* kfd = kf + ((size_t)bh * NSEL + j) * DHEAD;
        float* vfd = vf + ((size_t)bh * NSEL + j) * DHEAD;
        #pragma unroll
        for (int c = 0; c < DHEAD; c++) {
            kfd[c] = qkv[kbase + (size_t)c * HW + off];
            vfd[c] = qkv[vbase + (size_t)c * HW + off];
        }
    }
}

// ---------------- attention: softmax(q·k)·v, online, kf/vf in smem -----------
// q is read directly from the (in-place l2-normalized) qkv buffer: thread p's
// load of channel c is coalesced across the warp (consecutive p).
__global__ void attn_kernel(const float* __restrict__ qkv, const float* __restrict__ kf,
                            const float* __restrict__ vf, float* __restrict__ out) {
    extern __shared__ float sh[];
    float* kfs = sh;                    // 8192 floats
    float* vfs = sh + NSEL * DHEAD;     // 8192 floats
    int bh = blockIdx.y;
    int tid = threadIdx.x;
    int b = bh >> 3, hd = bh & 7;
    {
        const float4* ks = reinterpret_cast<const float4*>(kf + (size_t)bh * NSEL * DHEAD);
        const float4* vs = reinterpret_cast<const float4*>(vf + (size_t)bh * NSEL * DHEAD);
        float4* kd = reinterpret_cast<float4*>(kfs);
        float4* vd = reinterpret_cast<float4*>(vfs);
        for (int i = tid; i < NSEL * DHEAD / 4; i += 256) { kd[i] = ks[i]; vd[i] = vs[i]; }
    }
    __syncthreads();
    int p = blockIdx.x * 256 + tid;
    float q[DHEAD];
    {
        const float* qb = qkv + (size_t)(b * 3 * INNER + hd * DHEAD) * HW + p;
        #pragma unroll
        for (int c = 0; c < DHEAD; c++) q[c] = qb[(size_t)c * HW];
    }
    float m = -1e30f, l = 0.f;
    float acc[DHEAD];
    #pragma unroll
    for (int c = 0; c < DHEAD; c++) acc[c] = 0.f;

    for (int ch = 0; ch < NSEL / 32; ch++) {
        const float* kc = kfs + ch * 32 * DHEAD;
        const float* vc = vfs + ch * 32 * DHEAD;
        float s[32];
        #pragma unroll
        for (int jj = 0; jj < 32; jj++) {
            float d = 0.f;
            #pragma unroll
            for (int c = 0; c < DHEAD; c++) d += q[c] * kc[jj * DHEAD + c];
            s[jj] = d;
        }
        float cm = m;
        #pragma unroll
        for (int jj = 0; jj < 32; jj++) cm = fmaxf(cm, s[jj]);
        float scale = __expf(m - cm);
        l *= scale;
        #pragma unroll
        for (int c = 0; c < DHEAD; c++) acc[c] *= scale;
        #pragma unroll
        for (int jj = 0; jj < 32; jj++) {
            float e = __expf(s[jj] - cm);
            l += e;
            #pragma unroll
            for (int c = 0; c < DHEAD; c++) acc[c] += e * vc[jj * DHEAD + c];
        }
        m = cm;
    }
    float inv = 1.f / l;
    float* ob = out + (size_t)(b * INNER + hd * DHEAD) * HW + p;
    #pragma unroll
    for (int c = 0; c < DHEAD; c++) ob[(size_t)c * HW] = acc[c] * inv;
}

// ---------------- depthwise 3x3 (SAME, zero pad) -----------------------------
__global__ void dwconv_kernel(const float* __restrict__ in, const float* __restrict__ wt,
                              const float* __restrict__ bias, float* __restrict__ out,
                              int C, size_t outBatchStride, int outChanOffset) {
    int idx = blockIdx.x * 256 + threadIdx.x;
    int total = NB * C * HW;
    if (idx >= total) return;
    int w = idx & 63;
    int h = (idx >> 6) & 63;
    int bc = idx >> 12;
    int c = bc % C;
    int b = bc / C;
    const float* xp = in + ((size_t)bc << 12);
    const float* wp = wt + c * 9;
    float acc = bias[c];
    #pragma unroll
    for (int di = 0; di < 3; di++) {
        int hh2 = h + di - 1;
        if (hh2 < 0 || hh2 > 63) continue;
        #pragma unroll
        for (int dj = 0; dj < 3; dj++) {
            int ww2 = w + dj - 1;
            if (ww2 < 0 || ww2 > 63) continue;
            acc += xp[hh2 * 64 + ww2] * wp[di * 3 + dj];
        }
    }
    out[(size_t)b * outBatchStride + (size_t)(outChanOffset + c) * HW + (idx & 4095)] = acc;
}

// ---------------- instance norm (+optional exact gelu, +optional residual) ---
template<bool GELU, bool RES>
__global__ void instnorm_kernel(const float* __restrict__ in, float* __restrict__ out,
                                const float* __restrict__ res) {
    __shared__ float sbufA[8];
    __shared__ float sbufB[8];
    __shared__ float s_mean, s_rstd;
    int bc = blockIdx.x;
    int tid = threadIdx.x;
    const float4* x4 = reinterpret_cast<const float4*>(in + (size_t)bc * HW);
    float s = 0.f, ss = 0.f;
    #pragma unroll
    for (int k = 0; k < 4; k++) {
        float4 v = x4[tid + k * 256];
        s  += v.x + v.y + v.z + v.w;
        ss += v.x * v.x + v.y * v.y + v.z * v.z + v.w * v.w;
    }
    #pragma unroll
    for (int o = 16; o > 0; o >>= 1) {
        s  += __shfl_xor_sync(0xffffffffu, s,  o);
        ss += __shfl_xor_sync(0xffffffffu, ss, o);
    }
    if ((tid & 31) == 0) { sbufA[tid >> 5] = s; sbufB[tid >> 5] = ss; }
    __syncthreads();
    if (tid == 0) {
        float a = 0.f, b2 = 0.f;
        for (int i = 0; i < 8; i++) { a += sbufA[i]; b2 += sbufB[i]; }
        float mean = a * (1.f / HW);
        float var  = b2 * (1.f / HW) - mean * mean;
        s_mean = mean;
        s_rstd = rsqrtf(var + 1e-5f);
    }
    __syncthreads();
    float mean = s_mean, rstd = s_rstd;
    float4* o4 = reinterpret_cast<float4*>(out + (size_t)bc * HW);
    const float4* r4 = RES ? reinterpret_cast<const float4*>(res + (size_t)bc * HW) : nullptr;
    #pragma unroll
    for (int k = 0; k < 4; k++) {
        float4 v = x4[tid + k * 256];
        float t[4] = {v.x, v.y, v.z, v.w};
        #pragma unroll
        for (int e = 0; e < 4; e++) {
            float y = (t[e] - mean) * rstd;
            if (GELU) y = 0.5f * y * (1.f + erff(y * 0.70710678118654752f));
            t[e] = y;
        }
        float4 ov = {t[0], t[1], t[2], t[3]};
        if (RES) {
            float4 rv = r4[tid + k * 256];
            ov.x += rv.x; ov.y += rv.y; ov.z += rv.z; ov.w += rv.w;
        }
        o4[tid + k * 256] = ov;
    }
}

// ---------------- host orchestration ----------------------------------------
extern "C" void kernel_launch(void* const* d_in, const int* in_sizes, int n_in,
                              void* d_out, int out_size) {
    const float* x      = (const float*)d_in[0];
    const float* ln_g   = (const float*)d_in[1];
    const float* ln_b   = (const float*)d_in[2];
    const float* w_qkv  = (const float*)d_in[3];
    const float* w_out  = (const float*)d_in[4];
    const float* b_out  = (const float*)d_in[5];
    const float* w_dw   = (const float*)d_in[6];
    const float* b_dw   = (const float*)d_in[7];
    const float* w_comb = (const float*)d_in[8];
    const float* b_comb = (const float*)d_in[9];
    const float* w_ff1  = (const float*)d_in[10];
    const float* b_ff1  = (const float*)d_in[11];
    const float* w_ffdw = (const float*)d_in[12];
    const float* b_ffdw = (const float*)d_in[13];
    const float* w_ff2  = (const float*)d_in[14];
    const float* b_ff2  = (const float*)d_in[15];
    float* out = (float*)d_out;

    float *p_xn, *p_qkv, *p_qrow, *p_kh, *p_qp, *p_kf, *p_vf;
    float *p_ai, *p_comb, *p_ao, *p_h1, *p_h, *p_c2, *p_ff2;
    int *p_toph, *p_topw;
    cudaGetSymbolAddress((void**)&p_xn, g_xn);
    cudaGetSymbolAddress((void**)&p_qkv, g_qkv);
    cudaGetSymbolAddress((void**)&p_qrow, g_qrow);
    cudaGetSymbolAddress((void**)&p_kh, g_kheight);
    cudaGetSymbolAddress((void**)&p_qp, g_qprobe);
    cudaGetSymbolAddress((void**)&p_toph, g_toph);
    cudaGetSymbolAddress((void**)&p_topw, g_topw);
    cudaGetSymbolAddress((void**)&p_kf, g_kf);
    cudaGetSymbolAddress((void**)&p_vf, g_vf);
    cudaGetSymbolAddress((void**)&p_ai, g_attninner);
    cudaGetSymbolAddress((void**)&p_comb, g_combined);
    cudaGetSymbolAddress((void**)&p_ao, g_attnout);
    cudaGetSymbolAddress((void**)&p_h1, g_h1);
    cudaGetSymbolAddress((void**)&p_h, g_h);
    cudaGetSymbolAddress((void**)&p_c2, g_c2);
    cudaGetSymbolAddress((void**)&p_ff2, g_ff2);

    // 1. channel layernorm
    ln_kernel<<<dim3(16, NB), 256>>>(x, ln_g, ln_b, p_xn);

    // 2. qkv = w_qkv @ xn   (768x256 @ 256x4096, per batch)
    sgemm<<<dim3(HW / 128, 768 / 128, NB), 256>>>(
        w_qkv, p_xn, p_qkv, nullptr, nullptr, 768, HW, 256,
        (size_t)256 * HW, (size_t)768 * HW, 0);

    // 3. l2norm q,k rows (in place) + row sums
    l2norm_kernel<<<32768, 256>>>(p_qkv, p_qrow, p_kh);

    // 4. q_probe + score_r + top-16 rows
    scorer_kernel<<<BHN, 64>>>(p_qrow, p_kh, p_qp, p_toph);

    // 5. k_width + score_c + top-16 cols + gather kf/vf
    select_gather_kernel<<<BHN, 256>>>(p_qkv, p_qp, p_toph, p_topw, p_kf, p_vf);

    // 6. attention core (q read directly from normalized qkv)
    cudaFuncSetAttribute(attn_kernel, cudaFuncAttributeMaxDynamicSharedMemorySize, 65536);
    attn_kernel<<<dim3(16, BHN), 256, 65536>>>(p_qkv, p_kf, p_vf, p_ai);

    // 7. attn_branch = w_out @ attninner + b_out  -> combined[:, 0:256]
    sgemm<<<dim3(HW / 128, 256 / 128, NB), 256>>>(
        w_out, p_ai, p_comb, b_out, nullptr, 256, HW, 256,
        (size_t)256 * HW, (size_t)512 * HW, 0);

    // 8. conv_branch = dwconv3x3(x) -> combined[:, 256:512]
    dwconv_kernel<<<(NB * 256 * HW) / 256, 256>>>(
        x, w_dw, b_dw, p_comb, 256, (size_t)512 * HW, 256);

    // 9. attn_out = w_comb @ combined + b_comb + x
    sgemm<<<dim3(HW / 128, 256 / 128, NB), 256>>>(
        w_comb, p_comb, p_ao, b_comb, x, 256, HW, 512,
        (size_t)512 * HW, (size_t)256 * HW, (size_t)256 * HW);

    // 10. h1 = w_ff1 @ attn_out + b_ff1
    sgemm<<<dim3(HW / 128, 1024 / 128, NB), 256>>>(
        w_ff1, p_ao, p_h1, b_ff1, nullptr, 1024, HW, 256,
        (size_t)256 * HW, (size_t)1024 * HW, 0);

    // 11. h = gelu(instnorm(h1))
    instnorm_kernel<true, false><<<NB * FFIC, 256>>>(p_h1, p_h, nullptr);

    // 12. c2 = dwconv3x3(h) + b_ffdw
    dwconv_kernel<<<(NB * FFIC * HW) / 256, 256>>>(
        p_h, w_ffdw, b_ffdw, p_c2, FFIC, (size_t)FFIC * HW, 0);

    // 13. h2 = gelu(instnorm(c2)) + h   (into h1, reused)
    instnorm_kernel<true, true><<<NB * FFIC, 256>>>(p_c2, p_h1, p_h);

    // 14. ff2 = w_ff2 @ h2 + b_ff2
    sgemm<<<dim3(HW / 128, 256 / 128, NB), 256>>>(
        w_ff2, p_h1, p_ff2, b_ff2, nullptr, 256, HW, 1024,
        (size_t)1024 * HW, (size_t)256 * HW, 0);

    // 15. out = instnorm(ff2)
    instnorm_kernel<false, false><<<NB * 256, 256>>>(p_ff2, out, nullptr);
}

// round 15
// speedup vs baseline: 1.0398x; 1.0398x over previous
#include <cuda_runtime.h>
#include <cuda_fp16.h>
#include <math.h>
#include <stdint.h>

#define NB 8
#define DIMC 256
#define HH 64
#define WW 64
#define HW 4096
#define NHEADS 8
#define DHEAD 32
#define INNER 256
#define BHN 64
#define FFIC 1024
#define TOPH 16
#define TOPW 16
#define NSEL 256

// ---------------- PTX helpers (baseline sm_80+ PTX only) ---------------------
__device__ __forceinline__ uint32_t smem_u32(const void* p) {
    uint32_t a;
    asm("{ .reg .u64 t; cvta.to.shared.u64 t, %1; cvt.u32.u64 %0, t; }" : "=r"(a) : "l"(p));
    return a;
}
#define LDSM_X4(r, addr) \
    asm volatile("ldmatrix.sync.aligned.m8n8.x4.shared.b16 {%0,%1,%2,%3}, [%4];" \
        : "=r"((r)[0]), "=r"((r)[1]), "=r"((r)[2]), "=r"((r)[3]) : "r"(addr))
#define LDSM_X2T(r, addr) \
    asm volatile("ldmatrix.sync.aligned.m8n8.x2.trans.shared.b16 {%0,%1}, [%2];" \
        : "=r"((r)[0]), "=r"((r)[1]) : "r"(addr))
#define MMA16816(c, a, b) \
    asm volatile("mma.sync.aligned.m16n8k16.row.col.f32.f16.f16.f32 " \
        "{%0,%1,%2,%3}, {%4,%5,%6,%7}, {%8,%9}, {%0,%1,%2,%3};" \
        : "+f"((c)[0]), "+f"((c)[1]), "+f"((c)[2]), "+f"((c)[3]) \
        : "r"((a)[0]), "r"((a)[1]), "r"((a)[2]), "r"((a)[3]), "r"((b)[0]), "r"((b)[1]))

// fp32 -> fp16 hi/lo split, packed pairs
__device__ __forceinline__ uint32_t pack2(float x, float y, uint32_t& lo) {
    __half hx = __float2half_rn(x), hy = __float2half_rn(y);
    __half lx = __float2half_rn(x - __half2float(hx));
    __half ly = __float2half_rn(y - __half2float(hy));
    lo = (uint32_t)__half_as_ushort(lx) | ((uint32_t)__half_as_ushort(ly) << 16);
    return (uint32_t)__half_as_ushort(hx) | ((uint32_t)__half_as_ushort(hy) << 16);
}

// ---------------- scratch (static device memory; no allocation allowed) ------
__device__ float g_xn[(size_t)NB*DIMC*HW];
__device__ float g_qkv[(size_t)NB*3*INNER*HW];
__device__ float g_qrow[BHN*DHEAD*HH];
__device__ float g_kheight[BHN*DHEAD*HH];
__device__ float g_qprobe[BHN*DHEAD];
__device__ int   g_toph[BHN*TOPH];
__device__ int   g_topw[BHN*TOPW];
__device__ float g_kf[BHN*NSEL*DHEAD];
__device__ float g_vf[BHN*NSEL*DHEAD];
__device__ float g_attninner[(size_t)NB*INNER*HW];
__device__ float g_combined[(size_t)NB*2*DIMC*HW];
__device__ float g_attnout[(size_t)NB*DIMC*HW];
__device__ float g_h1[(size_t)NB*FFIC*HW];
__device__ float g_h[(size_t)NB*FFIC*HW];
__device__ float g_c2[(size_t)NB*FFIC*HW];
__device__ float g_ff2[(size_t)NB*DIMC*HW];

// ---------------- channel layernorm ------------------------------------------
__global__ void ln_kernel(const float* __restrict__ x, const float* __restrict__ g,
                          const float* __restrict__ bb, float* __restrict__ out) {
    int pos = blockIdx.x * 256 + threadIdx.x;
    int b = blockIdx.y;
    const float* xb = x + (size_t)b * DIMC * HW + pos;
    float s = 0.f, ss = 0.f;
    #pragma unroll 8
    for (int c = 0; c < DIMC; c++) {
        float v = xb[(size_t)c * HW];
        s += v; ss += v * v;
    }
    float mean = s * (1.f / DIMC);
    float var  = ss * (1.f / DIMC) - mean * mean;
    float rstd = rsqrtf(var + 1e-5f);
    float* ob = out + (size_t)b * DIMC * HW + pos;
    #pragma unroll 8
    for (int c = 0; c < DIMC; c++) {
        float v = xb[(size_t)c * HW];
        ob[(size_t)c * HW] = (v - mean) * rstd * g[c] + bb[c];
    }
}

// ---------------- HMMA fp16-split GEMM ---------------------------------------
// C[bz][m][n] = sum_k A[m][k]*B[bz][k][n] (+bias[m]) (+resid[bz][m][n])
// CTA 128x128, K-step 32, double-buffered smem, warp tile 64x32 via m16n8k16.
// fp16 hi/lo 3-term split: ah*bh + ah*bl + al*bh  (fp32 accumulate).
// smem per stage (byte offsets): Ahi@0 (128x40h, 80B stride), Alo@10240,
//   Bhi@20480 (32x136h, 272B stride), Blo@29184. stage stride 38912, 2 stages.
#define TG_STAGE 38912
#define TG_SMEM  (2 * TG_STAGE)

__device__ __forceinline__ void tg_fill(const float* __restrict__ Ag,
                                        const float* __restrict__ Bg,
                                        char* dsmS, int K, int tid) {
    // A tile: 128 m x 32 k
    for (int i = tid; i < 1024; i += 256) {
        int m = i >> 3, k4 = (i & 7) << 2;
        float4 v = *reinterpret_cast<const float4*>(&Ag[(size_t)m * K + k4]);
        uint32_t l0, l1;
        uint32_t h0 = pack2(v.x, v.y, l0);
        uint32_t h1 = pack2(v.z, v.w, l1);
        char* ph = dsmS + m * 80 + k4 * 2;
        *reinterpret_cast<uint2*>(ph)         = make_uint2(h0, h1);
        *reinterpret_cast<uint2*>(ph + 10240) = make_uint2(l0, l1);
    }
    // B tile: 32 k x 128 n (kept [k][n]; consumed with ldmatrix.trans)
    for (int i = tid; i < 1024; i += 256) {
        int k = i >> 5, n4 = (i & 31) << 2;
        float4 v = *reinterpret_cast<const float4*>(&Bg[(size_t)k * HW + n4]);
        uint32_t l0, l1;
        uint32_t h0 = pack2(v.x, v.y, l0);
        uint32_t h1 = pack2(v.z, v.w, l1);
        char* ph = dsmS + 20480 + k * 272 + n4 * 2;
        *reinterpret_cast<uint2*>(ph)        = make_uint2(h0, h1);
        *reinterpret_cast<uint2*>(ph + 8704) = make_uint2(l0, l1);
    }
}

__global__ __launch_bounds__(256, 1)
void tgemm(const float* __restrict__ A, const float* __restrict__ B,
           float* __restrict__ C, const float* __restrict__ bias,
           const float* __restrict__ resid, int M, int K,
           size_t bStride, size_t cStride, size_t rStride)
{
    extern __shared__ __align__(1024) char dsm[];
    const int tid = threadIdx.x;
    const int wid = tid >> 5, lane = tid & 31;
    const int bz = blockIdx.z;
    const int mBase = blockIdx.y * 128, nBase = blockIdx.x * 128;
    const float* Ab = A + (size_t)mBase * K;
    const float* Bb = B + bz * bStride + nBase;
    float* Cb = C + bz * cStride;
    const float* Rb = resid ? resid + bz * rStride : nullptr;
    const uint32_t smem = smem_u32(dsm);

    const int wm = wid >> 2;      // 0..1 -> 64 m rows
    const int wn = wid & 3;       // 0..3 -> 32 n cols

    float acc[4][4][4];
    #pragma unroll
    for (int i = 0; i < 4; i++)
        #pragma unroll
        for (int j = 0; j < 4; j++)
            #pragma unroll
            for (int e = 0; e < 4; e++) acc[i][j][e] = 0.f;

    const int nT = K >> 5;
    tg_fill(Ab, Bb, dsm, K, tid);

    for (int kt = 0; kt < nT; kt++) {
        __syncthreads();
        if (kt + 1 < nT)
            tg_fill(Ab + (kt + 1) * 32, Bb + (size_t)((kt + 1) * 32) * HW,
                    dsm + ((kt + 1) & 1) * TG_STAGE, K, tid);

        const uint32_t sb = smem + (kt & 1) * TG_STAGE;
        const uint32_t aAddr = sb + (uint32_t)(wm * 64 + (lane & 15)) * 80 + ((lane >> 4) * 16);
        const uint32_t bAddr = sb + 20480 + (uint32_t)(lane & 15) * 272;

        #pragma unroll
        for (int kk2 = 0; kk2 < 2; kk2++) {     // two k16 halves of the k32 tile
            uint32_t ah[4][4], al[4][4];
            #pragma unroll
            for (int mf = 0; mf < 4; mf++) {
                uint32_t ad = aAddr + mf * 1280 + kk2 * 32;
                LDSM_X4(ah[mf], ad);
                LDSM_X4(al[mf], ad + 10240);
            }
            #pragma unroll
            for (int nf = 0; nf < 4; nf++) {
                uint32_t bd = bAddr + kk2 * 4352 + (wn * 32 + nf * 8) * 2;
                uint32_t bh[2], bl[2];
                LDSM_X2T(bh, bd);
                LDSM_X2T(bl, bd + 8704);
                #pragma unroll
                for (int mf = 0; mf < 4; mf++) {
                    MMA16816(acc[mf][nf], ah[mf], bh);
                    MMA16816(acc[mf][nf], ah[mf], bl);
                    MMA16816(acc[mf][nf], al[mf], bh);
                }
            }
        }
    }

    // epilogue: fragments -> global, fused bias/resid
    const int r = lane >> 2, cp = (lane & 3) * 2;
    #pragma unroll
    for (int mf = 0; mf < 4; mf++) {
        int m0 = mBase + wm * 64 + mf * 16 + r;
        float bv0 = bias ? bias[m0] : 0.f;
        float bv8 = bias ? bias[m0 + 8] : 0.f;
        #pragma unroll
        for (int nf = 0; nf < 4; nf++) {
            int n0 = nBase + wn * 32 + nf * 8 + cp;
            size_t o0 = (size_t)m0 * HW + n0;
            size_t o8 = (size_t)(m0 + 8) * HW + n0;
            float v0 = acc[mf][nf][0] + bv0;
            float v1 = acc[mf][nf][1] + bv0;
            float v2 = acc[mf][nf][2] + bv8;
            float v3 = acc[mf][nf][3] + bv8;
            if (Rb) {
                float2 r0 = *reinterpret_cast<const float2*>(&Rb[o0]);
                float2 r8 = *reinterpret_cast<const float2*>(&Rb[o8]);
                v0 += r0.x; v1 += r0.y; v2 += r8.x; v3 += r8.y;
            }
            *reinterpret_cast<float2*>(&Cb[o0]) = make_float2(v0, v1);
            *reinterpret_cast<float2*>(&Cb[o8]) = make_float2(v2, v3);
        }
    }
}

// ---------------- l2 norm along W for q/k rows + row sums --------------------
__global__ void l2norm_kernel(float* __restrict__ qkv, float* __restrict__ qrow,
                              float* __restrict__ kheight) {
    int gw   = (blockIdx.x * blockDim.x + threadIdx.x) >> 5;
    int lane = threadIdx.x & 31;
    const int RPP = BHN * DHEAD * HH;
    int part = (gw >= RPP) ? 1 : 0;
    int r = gw - part * RPP;
    int bh  = r / (DHEAD * HH);
    int rem = r % (DHEAD * HH);
    int c = rem / HH;
    int h = rem % HH;
    int b = bh >> 3, hd = bh & 7;
    int ch = part * INNER + hd * DHEAD + c;
    float* row = qkv + ((size_t)(b * 3 * INNER + ch) * HH + h) * WW;
    float x0 = row[lane], x1 = row[lane + 32];
    float ss = x0 * x0 + x1 * x1;
    #pragma unroll
    for (int o = 16; o > 0; o >>= 1) ss += __shfl_xor_sync(0xffffffffu, ss, o);
    float n  = sqrtf(ss);
    float sc = 1.f / fmaxf(n, 1e-12f);
    x0 *= sc; x1 *= sc;
    row[lane] = x0; row[lane + 32] = x1;
    float rs = x0 + x1;
    #pragma unroll
    for (int o = 16; o > 0; o >>= 1) rs += __shfl_xor_sync(0xffffffffu, rs, o);
    if (lane == 0) {
        float* dst = part ? kheight : qrow;
        dst[(bh * DHEAD + c) * HH + h] = rs;
    }
}

// ---------------- q_probe, score_r, top-16 rows ------------------------------
__global__ void scorer_kernel(const float* __restrict__ qrow, const float* __restrict__ kheight,
                              float* __restrict__ qprobe, int* __restrict__ toph) {
    __shared__ float qp[DHEAD];
    __shared__ float sc[HH];
    int bh = blockIdx.x;
    int tid = threadIdx.x;
    if (tid < DHEAD) {
        float s = 0.f;
        const float* qr = qrow + (bh * DHEAD + tid) * HH;
        for (int h = 0; h < HH; h++) s += qr[h];
        qp[tid] = s;
        qprobe[bh * DHEAD + tid] = s;
    }
    __syncthreads();
    if (tid < HH) {
        float s = 0.f;
        const float* kh = kheight + bh * DHEAD * HH;
        for (int c = 0; c < DHEAD; c++) s += qp[c] * kh[c * HH + tid];
        sc[tid] = s;
    }
    __syncthreads();
    if (tid == 0) {
        for (int i = 0; i < TOPH; i++) {
            float best = -INFINITY; int bi = 0;
            for (int h = 0; h < HH; h++) if (sc[h] > best) { best = sc[h]; bi = h; }
            toph[bh * TOPH + i] = bi;
            sc[bi] = -INFINITY;
        }
    }
}

// ---------------- k_width, score_c, top-16 cols, gather kf/vf ----------------
__global__ void select_gather_kernel(const float* __restrict__ qkv, const float* __restrict__ qprobe,
                                     const int* __restrict__ toph, int* __restrict__ topw,
                                     float* __restrict__ kf, float* __restrict__ vf) {
    __shared__ float kw[DHEAD * WW];
    __shared__ float sc[WW];
    __shared__ int th[TOPH];
    __shared__ int tw[TOPW];
    int bh = blockIdx.x;
    int tid = threadIdx.x;
    int b = bh >> 3, hd = bh & 7;
    if (tid < TOPH) th[tid] = toph[bh * TOPH + tid];
    __syncthreads();
    const size_t kbase = (size_t)(b * 3 * INNER + INNER + hd * DHEAD) * HW;
    for (int idx = tid; idx < DHEAD * WW; idx += 256) {
        int c = idx >> 6, w = idx & 63;
        float s = 0.f;
        #pragma unroll
        for (int i = 0; i < TOPH; i++)
            s += qkv[kbase + (size_t)c * HW + th[i] * WW + w];
        kw[idx] = s;
    }
    __syncthreads();
    if (tid < WW) {
        const float* qp = qprobe + bh * DHEAD;
        float s = 0.f;
        for (int c = 0; c < DHEAD; c++) s += qp[c] * kw[c * WW + tid];
        sc[tid] = s;
    }
    __syncthreads();
    if (tid == 0) {
        for (int i = 0; i < TOPW; i++) {
            float best = -INFINITY; int bi = 0;
            for (int w = 0; w < WW; w++) if (sc[w] > best) { best = sc[w]; bi = w; }
            tw[i] = bi; topw[bh * TOPW + i] = bi;
            sc[bi] = -INFINITY;
        }
    }
    __syncthreads();
    {
        const size_t vbase = (size_t)(b * 3 * INNER + 2 * INNER + hd * DHEAD) * HW;
        int j = tid;
        int hi = th[j >> 4];
        int wi = tw[j & 15];
        size_t off = (size_t)hi * WW + wi;
        float* kfd = kf + ((size_t)bh * NSEL + j) * DHEAD;
        float* vfd = vf + ((size_t)bh * NSEL + j) * DHEAD;
        #pragma unroll
        for (int c = 0; c < DHEAD; c++) {
            kfd[c] = qkv[kbase + (size_t)c * HW + off];
            vfd[c] = qkv[vbase + (size_t)c * HW + off];
        }
    }
}

// ---------------- attention: softmax(q·k)·v, online, kf/vf in smem -----------
__global__ void attn_kernel(const float* __restrict__ qkv, const float* __restrict__ kf,
                            const float* __restrict__ vf, float* __restrict__ out) {
    extern __shared__ float sh[];
    float* kfs = sh;
    float* vfs = sh + NSEL * DHEAD;
    int bh = blockIdx.y;
    int tid = threadIdx.x;
    int b = bh >> 3, hd = bh & 7;
    {
        const float4* ks = reinterpret_cast<const float4*>(kf + (size_t)bh * NSEL * DHEAD);
        const float4* vs = reinterpret_cast<const float4*>(vf + (size_t)bh * NSEL * DHEAD);
        float4* kd = reinterpret_cast<float4*>(kfs);
        float4* vd = reinterpret_cast<float4*>(vfs);
        for (int i = tid; i < NSEL * DHEAD / 4; i += 256) { kd[i] = ks[i]; vd[i] = vs[i]; }
    }
    __syncthreads();
    int p = blockIdx.x * 256 + tid;
    float q[DHEAD];
    {
        const float* qb = qkv + (size_t)(b * 3 * INNER + hd * DHEAD) * HW + p;
        #pragma unroll
        for (int c = 0; c < DHEAD; c++) q[c] = qb[(size_t)c * HW];
    }
    float m = -1e30f, l = 0.f;
    float acc[DHEAD];
    #pragma unroll
    for (int c = 0; c < DHEAD; c++) acc[c] = 0.f;

    for (int ch = 0; ch < NSEL / 32; ch++) {
        const float* kc = kfs + ch * 32 * DHEAD;
        const float* vc = vfs + ch * 32 * DHEAD;
        float s[32];
        #pragma unroll
        for (int jj = 0; jj < 32; jj++) {
            float d = 0.f;
            #pragma unroll
            for (int c = 0; c < DHEAD; c++) d += q[c] * kc[jj * DHEAD + c];
            s[jj] = d;
        }
        float cm = m;
        #pragma unroll
        for (int jj = 0; jj < 32; jj++) cm = fmaxf(cm, s[jj]);
        float scale = __expf(m - cm);
        l *= scale;
        #pragma unroll
        for (int c = 0; c < DHEAD; c++) acc[c] *= scale;
        #pragma unroll
        for (int jj = 0; jj < 32; jj++) {
            float e = __expf(s[jj] - cm);
            l += e;
            #pragma unroll
            for (int c = 0; c < DHEAD; c++) acc[c] += e * vc[jj * DHEAD + c];
        }
        m = cm;
    }
    float inv = 1.f / l;
    float* ob = out + (size_t)(b * INNER + hd * DHEAD) * HW + p;
    #pragma unroll
    for (int c = 0; c < DHEAD; c++) ob[(size_t)c * HW] = acc[c] * inv;
}

// ---------------- depthwise 3x3 (SAME, zero pad) -----------------------------
__global__ void dwconv_kernel(const float* __restrict__ in, const float* __restrict__ wt,
                              const float* __restrict__ bias, float* __restrict__ out,
                              int C, size_t outBatchStride, int outChanOffset) {
    int idx = blockIdx.x * 256 + threadIdx.x;
    int total = NB * C * HW;
    if (idx >= total) return;
    int w = idx & 63;
    int h = (idx >> 6) & 63;
    int bc = idx >> 12;
    int c = bc % C;
    int b = bc / C;
    const float* xp = in + ((size_t)bc << 12);
    const float* wp = wt + c * 9;
    float acc = bias[c];
    #pragma unroll
    for (int di = 0; di < 3; di++) {
        int hh2 = h + di - 1;
        if (hh2 < 0 || hh2 > 63) continue;
        #pragma unroll
        for (int dj = 0; dj < 3; dj++) {
            int ww2 = w + dj - 1;
            if (ww2 < 0 || ww2 > 63) continue;
            acc += xp[hh2 * 64 + ww2] * wp[di * 3 + dj];
        }
    }
    out[(size_t)b * outBatchStride + (size_t)(outChanOffset + c) * HW + (idx & 4095)] = acc;
}

// ---------------- instance norm (+optional exact gelu, +optional residual) ---
template<bool GELU, bool RES>
__global__ void instnorm_kernel(const float* __restrict__ in, float* __restrict__ out,
                                const float* __restrict__ res) {
    __shared__ float sbufA[8];
    __shared__ float sbufB[8];
    __shared__ float s_mean, s_rstd;
    int bc = blockIdx.x;
    int tid = threadIdx.x;
    const float4* x4 = reinterpret_cast<const float4*>(in + (size_t)bc * HW);
    float s = 0.f, ss = 0.f;
    #pragma unroll
    for (int k = 0; k < 4; k++) {
        float4 v = x4[tid + k * 256];
        s  += v.x + v.y + v.z + v.w;
        ss += v.x * v.x + v.y * v.y + v.z * v.z + v.w * v.w;
    }
    #pragma unroll
    for (int o = 16; o > 0; o >>= 1) {
        s  += __shfl_xor_sync(0xffffffffu, s,  o);
        ss += __shfl_xor_sync(0xffffffffu, ss, o);
    }
    if ((tid & 31) == 0) { sbufA[tid >> 5] = s; sbufB[tid >> 5] = ss; }
    __syncthreads();
    if (tid == 0) {
        float a = 0.f, b2 = 0.f;
        for (int i = 0; i < 8; i++) { a += sbufA[i]; b2 += sbufB[i]; }
        float mean = a * (1.f / HW);
        float var  = b2 * (1.f / HW) - mean * mean;
        s_mean = mean;
        s_rstd = rsqrtf(var + 1e-5f);
    }
    __syncthreads();
    float mean = s_mean, rstd = s_rstd;
    float4* o4 = reinterpret_cast<float4*>(out + (size_t)bc * HW);
    const float4* r4 = RES ? reinterpret_cast<const float4*>(res + (size_t)bc * HW) : nullptr;
    #pragma unroll
    for (int k = 0; k < 4; k++) {
        float4 v = x4[tid + k * 256];
        float t[4] = {v.x, v.y, v.z, v.w};
        #pragma unroll
        for (int e = 0; e < 4; e++) {
            float y = (t[e] - mean) * rstd;
            if (GELU) y = 0.5f * y * (1.f + erff(y * 0.70710678118654752f));
            t[e] = y;
        }
        float4 ov = {t[0], t[1], t[2], t[3]};
        if (RES) {
            float4 rv = r4[tid + k * 256];
            ov.x += rv.x; ov.y += rv.y; ov.z += rv.z; ov.w += rv.w;
        }
        o4[tid + k * 256] = ov;
    }
}

// ---------------- host orchestration ----------------------------------------
extern "C" void kernel_launch(void* const* d_in, const int* in_sizes, int n_in,
                              void* d_out, int out_size) {
    const float* x      = (const float*)d_in[0];
    const float* ln_g   = (const float*)d_in[1];
    const float* ln_b   = (const float*)d_in[2];
    const float* w_qkv  = (const float*)d_in[3];
    const float* w_out  = (const float*)d_in[4];
    const float* b_out  = (const float*)d_in[5];
    const float* w_dw   = (const float*)d_in[6];
    const float* b_dw   = (const float*)d_in[7];
    const float* w_comb = (const float*)d_in[8];
    const float* b_comb = (const float*)d_in[9];
    const float* w_ff1  = (const float*)d_in[10];
    const float* b_ff1  = (const float*)d_in[11];
    const float* w_ffdw = (const float*)d_in[12];
    const float* b_ffdw = (const float*)d_in[13];
    const float* w_ff2  = (const float*)d_in[14];
    const float* b_ff2  = (const float*)d_in[15];
    float* out = (float*)d_out;

    float *p_xn, *p_qkv, *p_qrow, *p_kh, *p_qp, *p_kf, *p_vf;
    float *p_ai, *p_comb, *p_ao, *p_h1, *p_h, *p_c2, *p_ff2;
    int *p_toph, *p_topw;
    cudaGetSymbolAddress((void**)&p_xn, g_xn);
    cudaGetSymbolAddress((void**)&p_qkv, g_qkv);
    cudaGetSymbolAddress((void**)&p_qrow, g_qrow);
    cudaGetSymbolAddress((void**)&p_kh, g_kheight);
    cudaGetSymbolAddress((void**)&p_qp, g_qprobe);
    cudaGetSymbolAddress((void**)&p_toph, g_toph);
    cudaGetSymbolAddress((void**)&p_topw, g_topw);
    cudaGetSymbolAddress((void**)&p_kf, g_kf);
    cudaGetSymbolAddress((void**)&p_vf, g_vf);
    cudaGetSymbolAddress((void**)&p_ai, g_attninner);
    cudaGetSymbolAddress((void**)&p_comb, g_combined);
    cudaGetSymbolAddress((void**)&p_ao, g_attnout);
    cudaGetSymbolAddress((void**)&p_h1, g_h1);
    cudaGetSymbolAddress((void**)&p_h, g_h);
    cudaGetSymbolAddress((void**)&p_c2, g_c2);
    cudaGetSymbolAddress((void**)&p_ff2, g_ff2);

    cudaFuncSetAttribute(tgemm, cudaFuncAttributeMaxDynamicSharedMemorySize, TG_SMEM);

    // 1. channel layernorm
    ln_kernel<<<dim3(16, NB), 256>>>(x, ln_g, ln_b, p_xn);

    // 2. qkv = w_qkv @ xn
    tgemm<<<dim3(HW / 128, 768 / 128, NB), 256, TG_SMEM>>>(
        w_qkv, p_xn, p_qkv, nullptr, nullptr, 768, 256,
        (size_t)256 * HW, (size_t)768 * HW, 0);

    // 3. l2norm q,k rows (in place) + row sums
    l2norm_kernel<<<32768, 256>>>(p_qkv, p_qrow, p_kh);

    // 4. q_probe + score_r + top-16 rows
    scorer_kernel<<<BHN, 64>>>(p_qrow, p_kh, p_qp, p_toph);

    // 5. k_width + score_c + top-16 cols + gather kf/vf
    select_gather_kernel<<<BHN, 256>>>(p_qkv, p_qp, p_toph, p_topw, p_kf, p_vf);

    // 6. attention core
    cudaFuncSetAttribute(attn_kernel, cudaFuncAttributeMaxDynamicSharedMemorySize, 65536);
    attn_kernel<<<dim3(16, BHN), 256, 65536>>>(p_qkv, p_kf, p_vf, p_ai);

    // 7. attn_branch = w_out @ attninner + b_out -> combined[:, 0:256]
    tgemm<<<dim3(HW / 128, 256 / 128, NB), 256, TG_SMEM>>>(
        w_out, p_ai, p_comb, b_out, nullptr, 256, 256,
        (size_t)256 * HW, (size_t)512 * HW, 0);

    // 8. conv_branch = dwconv3x3(x) -> combined[:, 256:512]
    dwconv_kernel<<<(NB * 256 * HW) / 256, 256>>>(
        x, w_dw, b_dw, p_comb, 256, (size_t)512 * HW, 256);

    // 9. attn_out = w_comb @ combined + b_comb + x
    tgemm<<<dim3(HW / 128, 256 / 128, NB), 256, TG_SMEM>>>(
        w_comb, p_comb, p_ao, b_comb, x, 256, 512,
        (size_t)512 * HW, (size_t)256 * HW, (size_t)256 * HW);

    // 10. h1 = w_ff1 @ attn_out + b_ff1
    tgemm<<<dim3(HW / 128, 1024 / 128, NB), 256, TG_SMEM>>>(
        w_ff1, p_ao, p_h1, b_ff1, nullptr, 1024, 256,
        (size_t)256 * HW, (size_t)1024 * HW, 0);

    // 11. h = gelu(instnorm(h1))
    instnorm_kernel<true, false><<<NB * FFIC, 256>>>(p_h1, p_h, nullptr);

    // 12. c2 = dwconv3x3(h) + b_ffdw
    dwconv_kernel<<<(NB * FFIC * HW) / 256, 256>>>(
        p_h, w_ffdw, b_ffdw, p_c2, FFIC, (size_t)FFIC * HW, 0);

    // 13. h2 = gelu(instnorm(c2)) + h
    instnorm_kernel<true, true><<<NB * FFIC, 256>>>(p_c2, p_h1, p_h);

    // 14. ff2 = w_ff2 @ h2 + b_ff2
    tgemm<<<dim3(HW / 128, 256 / 128, NB), 256, TG_SMEM>>>(
        w_ff2, p_h1, p_ff2, b_ff2, nullptr, 256, 1024,
        (size_t)1024 * HW, (size_t)256 * HW, 0);

    // 15. out = instnorm(ff2)
    instnorm_kernel<false, false><<<NB * 256, 256>>>(p_ff2, out, nullptr);
}